// round 8
// baseline (speedup 1.0000x reference)
#include <cuda_runtime.h>
#include <stdint.h>

#define NANCH 8732
#define NCLS 21
#define TOPK 200
#define CONF_TH 0.01f
#define NMS_TH 0.045f
#define MAXB 128
#define CANDCAP 2048u
#define TPC 4                 // tasks per CTA in kernel B
#define NTASKMAX (MAXB * (NCLS - 1))
#define T0BITS 0x3E000000u    // 0.125f
#define T0F 0.125f

// Scratch (no device allocs allowed):
__device__ float g_boxes[(size_t)MAXB * NANCH * 4];                   // [B,N,4]
__device__ unsigned long long g_cand[(size_t)NTASKMAX * CANDCAP];    // per-task lists
__device__ unsigned g_ccnt[NTASKMAX];                                 // per-task counts
__device__ unsigned g_fb[(size_t)(NTASKMAX / TPC) * NANCH];           // fallback scratch

// ---------------------------------------------------------------------------
__global__ void zero_counters_kernel() {
    int i = blockIdx.x * blockDim.x + threadIdx.x;
    if (i < NTASKMAX) g_ccnt[i] = 0u;
}

// ---------------------------------------------------------------------------
// Kernel A: softmax + decode + DIRECT candidate append (p >= 0.125).
// One thread per (b,n). probsT eliminated entirely.
// ---------------------------------------------------------------------------
__global__ void __launch_bounds__(256) softmax_decode_kernel(
        const float* __restrict__ loc,
        const float* __restrict__ conf,
        const float* __restrict__ anchors,
        int total) {
    __shared__ float sc[256 * NCLS];
    int base = blockIdx.x * 256;

    int gbase = base * NCLS;
    int navail = min(256 * NCLS, total * NCLS - gbase);
    for (int i = threadIdx.x; i < navail; i += 256)
        sc[i] = conf[gbase + i];
    __syncthreads();

    int idx = base + threadIdx.x;
    if (idx >= total) return;
    int b = idx / NANCH;
    int n = idx - b * NANCH;

    float v[NCLS];
    float mx = -1e30f;
#pragma unroll
    for (int c = 0; c < NCLS; c++) { v[c] = sc[threadIdx.x * NCLS + c]; mx = fmaxf(mx, v[c]); }
    float s = 0.0f;
#pragma unroll
    for (int c = 0; c < NCLS; c++) { v[c] = expf(v[c] - mx); s += v[c]; }
    float inv = 1.0f / s;

    unsigned enc = (unsigned)(~n);
#pragma unroll
    for (int c = 1; c < NCLS; c++) {
        float p = v[c] * inv;
        if (p >= T0F) {                    // implies p > CONF_TH
            int task = b * (NCLS - 1) + (c - 1);
            unsigned pos = atomicAdd(&g_ccnt[task], 1u);
            if (pos < CANDCAP)
                g_cand[(size_t)task * CANDCAP + pos] =
                    ((unsigned long long)__float_as_uint(p) << 32) | enc;
        }
    }

    float4 l4 = __ldg((const float4*)(loc) + idx);
    float4 a4 = __ldg((const float4*)(anchors) + n);
    float cx = a4.x + l4.x * 0.1f * a4.z;
    float cy = a4.y + l4.y * 0.1f * a4.w;
    float w  = a4.z * expf(l4.z * 0.2f);
    float h  = a4.w * expf(l4.w * 0.2f);
    float4 bb;
    bb.x = cx - 0.5f * w;
    bb.y = cy - 0.5f * h;
    bb.z = cx + 0.5f * w;
    bb.w = cy + 0.5f * h;
    ((float4*)g_boxes)[idx] = bb;
}

// ---------------------------------------------------------------------------
// Kernel B: 4 tasks per CTA. Per task: load prebuilt cand list (fallback:
// recompute softmax + adaptive collect), 3-pass radix select on list
// (bits [26:19],[18:11],[10:3]; bits[31:27]=00111 for p in (0.01,1]),
// exact 256-key bitonic sort. Then warps 0..3 run 4 serial NMS concurrently.
// ---------------------------------------------------------------------------
__global__ void __launch_bounds__(256, 5) topk_nms_kernel(
        const float* __restrict__ conf, float* __restrict__ out) {
    int tid = threadIdx.x;
    int lane = tid & 31, wrp = tid >> 5;

    __shared__ __align__(16) unsigned long long cand[CANDCAP];   // 16384 B
    __shared__ __align__(16) unsigned long long skey[256];       // 2048 B
    __shared__ __align__(16) unsigned shist[256];                // 1024 B
    __shared__ __align__(16) float4 sbx4[TPC][TOPK];             // 12800 B
    __shared__ float  sarea[TPC][TOPK];                          // 3200 B
    __shared__ float  sscore[TPC][TOPK];                         // 3200 B
    __shared__ unsigned keepmask[TPC][7];
    __shared__ unsigned k_sh, bin_sh, ccnt, scnt;

    // ================= per-task select phase (all 8 warps) =================
#pragma unroll 1
    for (int s = 0; s < TPC; s++) {
        int task = blockIdx.x * TPC + s;
        int b = task / (NCLS - 1);
        int c = task % (NCLS - 1);        // 0..19 -> output class c+1

        unsigned cc = g_ccnt[task];
        if (cc >= (unsigned)TOPK && cc <= CANDCAP) {
            // ---- main path: list already built by kernel A ----
            const unsigned long long* gl = g_cand + (size_t)task * CANDCAP;
            for (unsigned i = tid; i < cc; i += 256)
                cand[i] = gl[i];
        } else {
            // ---- fallback (≈never): recompute masked scores, adaptive collect
            unsigned* fb = g_fb + (size_t)blockIdx.x * NANCH;
            for (int n = tid; n < NANCH; n += 256) {
                const float* cp = conf + ((size_t)b * NANCH + n) * NCLS;
                float mx = -1e30f;
                float vv[NCLS];
#pragma unroll
                for (int q = 0; q < NCLS; q++) { vv[q] = cp[q]; mx = fmaxf(mx, vv[q]); }
                float sum = 0.f;
#pragma unroll
                for (int q = 0; q < NCLS; q++) sum += expf(vv[q] - mx);
                float p = expf(vv[c + 1] - mx) / sum;
                fb[n] = (p > CONF_TH) ? __float_as_uint(p) : 0u;
            }
            __syncthreads();
            unsigned lo = 0u, hi = 0x3F800001u, T = T0BITS;
            for (int attempt = 0; attempt < 24; attempt++) {
                if (tid == 0) ccnt = 0u;
                __syncthreads();
                for (int n0 = 0; n0 < NANCH; n0 += 256) {
                    int n = n0 + tid;
                    unsigned u = (n < NANCH) ? fb[n] : 0u;
                    bool pred = (u >= T);
                    unsigned mask = __ballot_sync(0xffffffffu, pred);
                    if (mask) {
                        int leader = __ffs(mask) - 1;
                        unsigned basev = 0u;
                        if (lane == leader) basev = atomicAdd(&ccnt, (unsigned)__popc(mask));
                        basev = __shfl_sync(0xffffffffu, basev, leader);
                        if (pred) {
                            unsigned pos = basev + (unsigned)__popc(mask & ((1u << lane) - 1u));
                            if (pos < CANDCAP)
                                cand[pos] = ((unsigned long long)u << 32) | (unsigned)(~n);
                        }
                    }
                }
                __syncthreads();
                cc = ccnt;
                if (cc <= CANDCAP && (cc >= (unsigned)TOPK || T <= 1u)) break;
                if (cc > CANDCAP) lo = T; else hi = T;
                if (hi <= lo + 1u) { T = (lo > 0u) ? lo : 1u; continue; }
                T = lo + ((hi - lo) >> 1);
                if (T == 0u) T = 1u;
            }
            if (cc > CANDCAP) cc = CANDCAP;
        }

        // ---- 3-pass radix select over the list ----
        shist[tid] = 0u;
        if (tid == 0) { k_sh = TOPK; bin_sh = 0u; }
        __syncthreads();

        unsigned prefix = 0u, pmask = 0u, bin0 = 0u;
#pragma unroll
        for (int pass = 0; pass < 3; pass++) {
            const int shift = (pass == 0) ? 19 : (pass == 1) ? 11 : 3;
            for (unsigned i = tid; i < cc; i += 256) {
                unsigned u = (unsigned)(cand[i] >> 32);
                if ((u & pmask) == prefix) atomicAdd(&shist[(u >> shift) & 255u], 1u);
            }
            __syncthreads();
            if (tid < 32) {
                uint4 h0 = ((const uint4*)shist)[tid * 2];
                uint4 h1 = ((const uint4*)shist)[tid * 2 + 1];
                unsigned local[8] = {h0.x, h0.y, h0.z, h0.w, h1.x, h1.y, h1.z, h1.w};
                unsigned lsum = 0;
#pragma unroll
                for (int j = 0; j < 8; j++) lsum += local[j];
                unsigned ssum = lsum;
#pragma unroll
                for (int off = 1; off < 32; off <<= 1) {
                    unsigned vv = __shfl_down_sync(0xffffffffu, ssum, off);
                    if (tid + off < 32) ssum += vv;
                }
                unsigned k = k_sh;
                unsigned run = ssum - lsum;
                unsigned fbin = 0u, fk = 0u;
#pragma unroll
                for (int j = 7; j >= 0; j--) {
                    unsigned prev = run;
                    run += local[j];
                    if (run >= k && prev < k) { fbin = (unsigned)(tid * 8 + j); fk = k - prev; }
                }
                unsigned bmax = __reduce_max_sync(0xffffffffu, fbin);
                unsigned kmax = __reduce_max_sync(0xffffffffu, fk);
                if (tid == 0) {
                    bin_sh = bmax;
                    if (kmax) k_sh = kmax;
                }
            }
            __syncthreads();
            unsigned bin = bin_sh;
            if (pass == 0) bin0 = bin;
            prefix |= bin << shift;
            pmask  |= 255u << shift;
            shist[tid] = 0u;
            __syncthreads();
        }
        unsigned Plo = 0x38000000u | prefix;
        if (bin0 == 0u) Plo = 1u;           // degenerate: <TOPK entries

        // ---- collect u >= Plo from list into skey (<=256 incl. slack) ----
        skey[tid] = 0ULL;
        if (tid == 0) scnt = 0u;
        __syncthreads();
        unsigned ccPad = (cc + 255u) & ~255u;
        for (unsigned i = tid; i < ccPad; i += 256) {
            unsigned long long kk = (i < cc) ? cand[i] : 0ULL;
            bool pred = ((unsigned)(kk >> 32) >= Plo);
            unsigned mask = __ballot_sync(0xffffffffu, pred);
            if (mask) {
                int leader = __ffs(mask) - 1;
                unsigned basev = 0u;
                if (lane == leader) basev = atomicAdd(&scnt, (unsigned)__popc(mask));
                basev = __shfl_sync(0xffffffffu, basev, leader);
                if (pred) {
                    unsigned pos = basev + (unsigned)__popc(mask & ((1u << lane) - 1u));
                    if (pos < 256u) skey[pos] = kk;
                }
            }
        }
        __syncthreads();

        // ---- bitonic sort 256 keys descending (value desc, idx asc) ----
        unsigned long long key = skey[tid];
#pragma unroll
        for (int ks = 2; ks <= 256; ks <<= 1) {
#pragma unroll
            for (int st = ks >> 1; st > 0; st >>= 1) {
                bool up = ((tid & ks) == 0);
                unsigned long long other;
                if (st >= 32) {
                    skey[tid] = key;
                    __syncthreads();
                    other = skey[tid ^ st];
                    __syncthreads();
                } else {
                    other = __shfl_xor_sync(0xffffffffu, key, st);
                }
                bool iLow = ((tid & st) == 0);
                bool takeMax = (iLow == up);
                bool otherBigger = (other > key);
                if (takeMax == otherBigger) key = other;
            }
        }

        // ---- stash this task's top-200 into per-task smem ----
        int keepf = 0;
        if (tid < TOPK) {
            float score = 0.f, x1 = 0.f, y1 = 0.f, x2 = 0.f, y2 = 0.f, area = 0.f;
            unsigned vb = (unsigned)(key >> 32);
            if (vb != 0u) {
                unsigned n = ~(unsigned)(key & 0xFFFFFFFFu);
                score = __uint_as_float(vb);
                float4 bp = ((const float4*)g_boxes)[(size_t)b * NANCH + n];
                x1 = bp.x; y1 = bp.y; x2 = bp.z; y2 = bp.w;
                area = (x2 - x1) * (y2 - y1);
                keepf = 1;
            }
            float4 bb; bb.x = x1; bb.y = y1; bb.z = x2; bb.w = y2;
            sbx4[s][tid] = bb;
            sarea[s][tid] = area;
            sscore[s][tid] = score;
        }
        {
            unsigned bal = __ballot_sync(0xffffffffu, keepf);
            if (lane == 0 && wrp < 7) keepmask[s][wrp] = bal;
        }
        __syncthreads();   // protects cand/shist/counters reuse next task
    }

    // ============ NMS phase: warps 0..3 run 4 serial NMS concurrently =======
    if (wrp < TPC) {
        const int s = wrp;
        unsigned keep[7];
#pragma unroll
        for (int t = 0; t < 7; t++) keep[t] = keepmask[s][t];

        for (int t = 0; t < 7; t++) {
            unsigned rem = keep[t];
            while (rem) {
                int bpos = __ffs(rem) - 1;
                int j = t * 32 + bpos;                 // kept pivot
                float4 pb = sbx4[s][j];                // broadcast LDS
                float pa = sarea[s][j];
#pragma unroll
                for (int tt = 0; tt < 7; tt++) {
                    if (tt >= t && keep[tt]) {         // warp-uniform skip
                        int jj = tt * 32 + lane;
                        float4 ob; float oa;
                        if (jj < TOPK) { ob = sbx4[s][jj]; oa = sarea[s][jj]; }
                        else { ob.x = 0.f; ob.y = 0.f; ob.z = -1.f; ob.w = -1.f; oa = 0.f; }
                        float ix1 = fmaxf(pb.x, ob.x);
                        float iy1 = fmaxf(pb.y, ob.y);
                        float ix2 = fminf(pb.z, ob.z);
                        float iy2 = fminf(pb.w, ob.w);
                        float iw = fmaxf(ix2 - ix1, 0.0f);
                        float ih = fmaxf(iy2 - iy1, 0.0f);
                        float inter = iw * ih;
                        float iou = inter / (pa + oa - inter + 1e-12f);
                        unsigned sup = __ballot_sync(0xffffffffu, iou > NMS_TH);
                        if (tt == t) sup &= ~((2u << bpos) - 1u);   // only bits > bpos
                        keep[tt] &= ~sup;
                    }
                }
                rem = keep[t] & ~((2u << bpos) - 1u);
            }
        }
        if (lane < 7) keepmask[s][lane] = keep[lane];
    }
    __syncthreads();

    // ============ pack phase: stable compaction + output write ==============
#pragma unroll
    for (int s = 0; s < TPC; s++) {
        int task = blockIdx.x * TPC + s;
        int b = task / (NCLS - 1);
        int c = task % (NCLS - 1);
        if (tid < TOPK) {
            unsigned km = keepmask[s][wrp];
            if ((km >> lane) & 1u) {
                int pos = __popc(km & ((1u << lane) - 1u));
#pragma unroll
                for (int q = 0; q < 6; q++)
                    if (q < wrp) pos += __popc(keepmask[s][q]);
                float4 bb = sbx4[s][tid];
                float* orow = out + ((((size_t)b * NCLS + (c + 1)) * TOPK) + pos) * 5;
                orow[0] = sscore[s][tid];
                orow[1] = bb.x; orow[2] = bb.y; orow[3] = bb.z; orow[4] = bb.w;
            }
        }
    }
}

// ---------------------------------------------------------------------------
extern "C" void kernel_launch(void* const* d_in, const int* in_sizes, int n_in,
                              void* d_out, int out_size) {
    const float* loc     = (const float*)d_in[0];  // [B,N,4]
    const float* conf    = (const float*)d_in[1];  // [B,N,21]
    const float* anchors = (const float*)d_in[2];  // [N,4]
    float* out = (float*)d_out;                    // [B,21,200,5]

    int total = in_sizes[0] / 4;          // B*N
    int B = total / NANCH;
    if (B > MAXB) B = MAXB;
    total = B * NANCH;

    cudaMemsetAsync(d_out, 0, (size_t)out_size * sizeof(float), 0);

    zero_counters_kernel<<<(NTASKMAX + 255) / 256, 256>>>();
    softmax_decode_kernel<<<(total + 255) / 256, 256>>>(loc, conf, anchors, total);
    int ntask = B * (NCLS - 1);                    // divisible by 4 (20 | ntask)
    topk_nms_kernel<<<ntask / TPC, 256>>>(conf, out);
}

// round 9
// speedup vs baseline: 2.2592x; 2.2592x over previous
#include <cuda_runtime.h>
#include <stdint.h>

#define NANCH 8732
#define NCLS 21
#define TOPK 200
#define CONF_TH 0.01f
#define NMS_TH 0.045f
#define MAXB 128
#define CANDCAP 2048u
#define TPC 4                 // tasks per CTA in kernel B
#define NTASKMAX (MAXB * (NCLS - 1))
#define T0BITS 0x3E000000u    // 0.125f
#define T0F 0.125f
#define NBLK 35               // ceil(8732/256) anchor-blocks per image
#define LCAP 64               // per-CTA per-class smem list capacity

// Scratch (no device allocs allowed):
__device__ float g_boxes[(size_t)MAXB * NANCH * 4];                   // [B,N,4]
__device__ unsigned long long g_cand[(size_t)NTASKMAX * CANDCAP];     // per-task lists
__device__ unsigned g_ccnt[NTASKMAX];                                 // per-task counts
__device__ unsigned g_fb[(size_t)(NTASKMAX / TPC) * NANCH];           // fallback scratch

// ---------------------------------------------------------------------------
__global__ void zero_counters_kernel() {
    int i = blockIdx.x * blockDim.x + threadIdx.x;
    if (i < NTASKMAX) g_ccnt[i] = 0u;
}

// ---------------------------------------------------------------------------
// Kernel A: softmax + decode + smem-aggregated candidate append (p >= 0.125).
// Grid: (NBLK, B). Each CTA covers 256 anchors of ONE image, so per-class
// smem lists aggregate cleanly; flush = 1 global atomic per class per CTA
// with coalesced g_cand writes.
// ---------------------------------------------------------------------------
__global__ void __launch_bounds__(256) softmax_decode_kernel(
        const float* __restrict__ loc,
        const float* __restrict__ conf,
        const float* __restrict__ anchors) {
    __shared__ float sc[256 * NCLS];                         // 21504 B
    __shared__ unsigned long long slist[NCLS - 1][LCAP];     // 10240 B
    __shared__ unsigned scnt_s[NCLS - 1];

    int b = blockIdx.y;
    int n0 = blockIdx.x * 256;
    int n = n0 + threadIdx.x;
    int tid = threadIdx.x;

    if (tid < NCLS - 1) scnt_s[tid] = 0u;

    // stage conf for this CTA's anchors (coalesced)
    int nanch_here = min(256, NANCH - n0);
    int navail = nanch_here * NCLS;
    size_t gbase = ((size_t)b * NANCH + n0) * NCLS;
    for (int i = tid; i < navail; i += 256)
        sc[i] = conf[gbase + i];
    __syncthreads();

    if (n < NANCH) {
        float v[NCLS];
        float mx = -1e30f;
#pragma unroll
        for (int c = 0; c < NCLS; c++) { v[c] = sc[tid * NCLS + c]; mx = fmaxf(mx, v[c]); }
        float s = 0.0f;
#pragma unroll
        for (int c = 0; c < NCLS; c++) { v[c] = expf(v[c] - mx); s += v[c]; }
        float inv = 1.0f / s;

        unsigned enc = (unsigned)(~n);
#pragma unroll
        for (int c = 1; c < NCLS; c++) {
            float p = v[c] * inv;
            if (p >= T0F) {                    // implies p > CONF_TH
                unsigned long long key =
                    ((unsigned long long)__float_as_uint(p) << 32) | enc;
                unsigned pos = atomicAdd(&scnt_s[c - 1], 1u);
                if (pos < LCAP) {
                    slist[c - 1][pos] = key;
                } else {                       // spill (≈never): direct global
                    int task = b * (NCLS - 1) + (c - 1);
                    unsigned gp = atomicAdd(&g_ccnt[task], 1u);
                    if (gp < CANDCAP) g_cand[(size_t)task * CANDCAP + gp] = key;
                }
            }
        }

        // decode boxes
        int idx = b * NANCH + n;
        float4 l4 = __ldg((const float4*)(loc) + idx);
        float4 a4 = __ldg((const float4*)(anchors) + n);
        float cx = a4.x + l4.x * 0.1f * a4.z;
        float cy = a4.y + l4.y * 0.1f * a4.w;
        float w  = a4.z * expf(l4.z * 0.2f);
        float h  = a4.w * expf(l4.w * 0.2f);
        float4 bb;
        bb.x = cx - 0.5f * w;
        bb.y = cy - 0.5f * h;
        bb.z = cx + 0.5f * w;
        bb.w = cy + 0.5f * h;
        ((float4*)g_boxes)[idx] = bb;
    }
    __syncthreads();

    // flush smem lists: warp w handles classes w, w+8, ... (coalesced writes)
    int lane = tid & 31, wrp = tid >> 5;
    for (int cl = wrp; cl < NCLS - 1; cl += 8) {
        unsigned cnt = min(scnt_s[cl], (unsigned)LCAP);
        int task = b * (NCLS - 1) + cl;
        unsigned basep = 0u;
        if (lane == 0 && cnt) basep = atomicAdd(&g_ccnt[task], cnt);
        basep = __shfl_sync(0xffffffffu, basep, 0);
        for (unsigned i = lane; i < cnt; i += 32) {
            unsigned gp = basep + i;
            if (gp < CANDCAP) g_cand[(size_t)task * CANDCAP + gp] = slist[cl][i];
        }
    }
}

// ---------------------------------------------------------------------------
// Kernel B: 4 tasks per CTA. Per task: load prebuilt cand list (fallback:
// lean softmax recompute + adaptive collect), 3-pass radix select on list
// (bits [26:19],[18:11],[10:3]; bits[31:27]=00111 for p in (0.01,1]),
// exact 256-key bitonic sort. Then warps 0..3 run 4 serial NMS concurrently.
// ---------------------------------------------------------------------------
__global__ void __launch_bounds__(256, 5) topk_nms_kernel(
        const float* __restrict__ conf, float* __restrict__ out) {
    int tid = threadIdx.x;
    int lane = tid & 31, wrp = tid >> 5;

    __shared__ __align__(16) unsigned long long cand[CANDCAP];   // 16384 B
    __shared__ __align__(16) unsigned long long skey[256];       // 2048 B
    __shared__ __align__(16) unsigned shist[256];                // 1024 B
    __shared__ __align__(16) float4 sbx4[TPC][TOPK];             // 12800 B
    __shared__ float  sarea[TPC][TOPK];                          // 3200 B
    __shared__ float  sscore[TPC][TOPK];                         // 3200 B
    __shared__ unsigned keepmask[TPC][7];
    __shared__ unsigned k_sh, bin_sh, ccnt, scnt;

    // ================= per-task select phase (all 8 warps) =================
#pragma unroll 1
    for (int s = 0; s < TPC; s++) {
        int task = blockIdx.x * TPC + s;
        int b = task / (NCLS - 1);
        int c = task % (NCLS - 1);        // 0..19 -> output class c+1

        unsigned cc = g_ccnt[task];
        if (cc >= (unsigned)TOPK && cc <= CANDCAP) {
            // ---- main path: list already built by kernel A ----
            const unsigned long long* gl = g_cand + (size_t)task * CANDCAP;
            for (unsigned i = tid; i < cc; i += 256)
                cand[i] = gl[i];
        } else {
            // ---- fallback (≈never): lean two-pass softmax recompute ----
            unsigned* fb = g_fb + (size_t)blockIdx.x * NANCH;
#pragma unroll 1
            for (int n = tid; n < NANCH; n += 256) {
                const float* cp = conf + ((size_t)b * NANCH + n) * NCLS;
                float mx = -1e30f;
#pragma unroll 1
                for (int q = 0; q < NCLS; q++) mx = fmaxf(mx, __ldg(cp + q));
                float sum = 0.f;
#pragma unroll 1
                for (int q = 0; q < NCLS; q++) sum += expf(__ldg(cp + q) - mx);
                float p = expf(__ldg(cp + c + 1) - mx) / sum;
                fb[n] = (p > CONF_TH) ? __float_as_uint(p) : 0u;
            }
            __syncthreads();
            unsigned lo = 0u, hi = 0x3F800001u, T = T0BITS;
#pragma unroll 1
            for (int attempt = 0; attempt < 24; attempt++) {
                if (tid == 0) ccnt = 0u;
                __syncthreads();
#pragma unroll 1
                for (int n0 = 0; n0 < NANCH; n0 += 256) {
                    int n = n0 + tid;
                    unsigned u = (n < NANCH) ? fb[n] : 0u;
                    bool pred = (u >= T);
                    unsigned mask = __ballot_sync(0xffffffffu, pred);
                    if (mask) {
                        int leader = __ffs(mask) - 1;
                        unsigned basev = 0u;
                        if (lane == leader) basev = atomicAdd(&ccnt, (unsigned)__popc(mask));
                        basev = __shfl_sync(0xffffffffu, basev, leader);
                        if (pred) {
                            unsigned pos = basev + (unsigned)__popc(mask & ((1u << lane) - 1u));
                            if (pos < CANDCAP)
                                cand[pos] = ((unsigned long long)u << 32) | (unsigned)(~n);
                        }
                    }
                }
                __syncthreads();
                cc = ccnt;
                if (cc <= CANDCAP && (cc >= (unsigned)TOPK || T <= 1u)) break;
                if (cc > CANDCAP) lo = T; else hi = T;
                if (hi <= lo + 1u) { T = (lo > 0u) ? lo : 1u; continue; }
                T = lo + ((hi - lo) >> 1);
                if (T == 0u) T = 1u;
            }
            if (cc > CANDCAP) cc = CANDCAP;
        }

        // ---- 3-pass radix select over the list ----
        shist[tid] = 0u;
        if (tid == 0) { k_sh = TOPK; bin_sh = 0u; }
        __syncthreads();

        unsigned prefix = 0u, pmask = 0u, bin0 = 0u;
#pragma unroll
        for (int pass = 0; pass < 3; pass++) {
            const int shift = (pass == 0) ? 19 : (pass == 1) ? 11 : 3;
            for (unsigned i = tid; i < cc; i += 256) {
                unsigned u = (unsigned)(cand[i] >> 32);
                if ((u & pmask) == prefix) atomicAdd(&shist[(u >> shift) & 255u], 1u);
            }
            __syncthreads();
            if (tid < 32) {
                uint4 h0 = ((const uint4*)shist)[tid * 2];
                uint4 h1 = ((const uint4*)shist)[tid * 2 + 1];
                unsigned local[8] = {h0.x, h0.y, h0.z, h0.w, h1.x, h1.y, h1.z, h1.w};
                unsigned lsum = 0;
#pragma unroll
                for (int j = 0; j < 8; j++) lsum += local[j];
                unsigned ssum = lsum;
#pragma unroll
                for (int off = 1; off < 32; off <<= 1) {
                    unsigned vv = __shfl_down_sync(0xffffffffu, ssum, off);
                    if (tid + off < 32) ssum += vv;
                }
                unsigned k = k_sh;
                unsigned run = ssum - lsum;
                unsigned fbin = 0u, fk = 0u;
#pragma unroll
                for (int j = 7; j >= 0; j--) {
                    unsigned prev = run;
                    run += local[j];
                    if (run >= k && prev < k) { fbin = (unsigned)(tid * 8 + j); fk = k - prev; }
                }
                unsigned bmax = __reduce_max_sync(0xffffffffu, fbin);
                unsigned kmax = __reduce_max_sync(0xffffffffu, fk);
                if (tid == 0) {
                    bin_sh = bmax;
                    if (kmax) k_sh = kmax;
                }
            }
            __syncthreads();
            unsigned bin = bin_sh;
            if (pass == 0) bin0 = bin;
            prefix |= bin << shift;
            pmask  |= 255u << shift;
            shist[tid] = 0u;
            __syncthreads();
        }
        unsigned Plo = 0x38000000u | prefix;
        if (bin0 == 0u) Plo = 1u;           // degenerate: <TOPK entries

        // ---- collect u >= Plo from list into skey (<=256 incl. slack) ----
        skey[tid] = 0ULL;
        if (tid == 0) scnt = 0u;
        __syncthreads();
        unsigned ccPad = (cc + 255u) & ~255u;
        for (unsigned i = tid; i < ccPad; i += 256) {
            unsigned long long kk = (i < cc) ? cand[i] : 0ULL;
            bool pred = ((unsigned)(kk >> 32) >= Plo);
            unsigned mask = __ballot_sync(0xffffffffu, pred);
            if (mask) {
                int leader = __ffs(mask) - 1;
                unsigned basev = 0u;
                if (lane == leader) basev = atomicAdd(&scnt, (unsigned)__popc(mask));
                basev = __shfl_sync(0xffffffffu, basev, leader);
                if (pred) {
                    unsigned pos = basev + (unsigned)__popc(mask & ((1u << lane) - 1u));
                    if (pos < 256u) skey[pos] = kk;
                }
            }
        }
        __syncthreads();

        // ---- bitonic sort 256 keys descending (value desc, idx asc) ----
        unsigned long long key = skey[tid];
#pragma unroll
        for (int ks = 2; ks <= 256; ks <<= 1) {
#pragma unroll
            for (int st = ks >> 1; st > 0; st >>= 1) {
                bool up = ((tid & ks) == 0);
                unsigned long long other;
                if (st >= 32) {
                    skey[tid] = key;
                    __syncthreads();
                    other = skey[tid ^ st];
                    __syncthreads();
                } else {
                    other = __shfl_xor_sync(0xffffffffu, key, st);
                }
                bool iLow = ((tid & st) == 0);
                bool takeMax = (iLow == up);
                bool otherBigger = (other > key);
                if (takeMax == otherBigger) key = other;
            }
        }

        // ---- stash this task's top-200 into per-task smem ----
        int keepf = 0;
        if (tid < TOPK) {
            float score = 0.f, x1 = 0.f, y1 = 0.f, x2 = 0.f, y2 = 0.f, area = 0.f;
            unsigned vb = (unsigned)(key >> 32);
            if (vb != 0u) {
                unsigned n = ~(unsigned)(key & 0xFFFFFFFFu);
                score = __uint_as_float(vb);
                float4 bp = ((const float4*)g_boxes)[(size_t)b * NANCH + n];
                x1 = bp.x; y1 = bp.y; x2 = bp.z; y2 = bp.w;
                area = (x2 - x1) * (y2 - y1);
                keepf = 1;
            }
            float4 bb; bb.x = x1; bb.y = y1; bb.z = x2; bb.w = y2;
            sbx4[s][tid] = bb;
            sarea[s][tid] = area;
            sscore[s][tid] = score;
        }
        {
            unsigned bal = __ballot_sync(0xffffffffu, keepf);
            if (lane == 0 && wrp < 7) keepmask[s][wrp] = bal;
        }
        __syncthreads();   // protects cand/shist/counters reuse next task
    }

    // ============ NMS phase: warps 0..3 run 4 serial NMS concurrently =======
    if (wrp < TPC) {
        const int s = wrp;
        unsigned keep[7];
#pragma unroll
        for (int t = 0; t < 7; t++) keep[t] = keepmask[s][t];

        for (int t = 0; t < 7; t++) {
            unsigned rem = keep[t];
            while (rem) {
                int bpos = __ffs(rem) - 1;
                int j = t * 32 + bpos;                 // kept pivot
                float4 pb = sbx4[s][j];                // broadcast LDS
                float pa = sarea[s][j];
#pragma unroll
                for (int tt = 0; tt < 7; tt++) {
                    if (tt >= t && keep[tt]) {         // warp-uniform skip
                        int jj = tt * 32 + lane;
                        float4 ob; float oa;
                        if (jj < TOPK) { ob = sbx4[s][jj]; oa = sarea[s][jj]; }
                        else { ob.x = 0.f; ob.y = 0.f; ob.z = -1.f; ob.w = -1.f; oa = 0.f; }
                        float ix1 = fmaxf(pb.x, ob.x);
                        float iy1 = fmaxf(pb.y, ob.y);
                        float ix2 = fminf(pb.z, ob.z);
                        float iy2 = fminf(pb.w, ob.w);
                        float iw = fmaxf(ix2 - ix1, 0.0f);
                        float ih = fmaxf(iy2 - iy1, 0.0f);
                        float inter = iw * ih;
                        float iou = inter / (pa + oa - inter + 1e-12f);
                        unsigned sup = __ballot_sync(0xffffffffu, iou > NMS_TH);
                        if (tt == t) sup &= ~((2u << bpos) - 1u);   // only bits > bpos
                        keep[tt] &= ~sup;
                    }
                }
                rem = keep[t] & ~((2u << bpos) - 1u);
            }
        }
        if (lane < 7) keepmask[s][lane] = keep[lane];
    }
    __syncthreads();

    // ============ pack phase: stable compaction + output write ==============
#pragma unroll
    for (int s = 0; s < TPC; s++) {
        int task = blockIdx.x * TPC + s;
        int b = task / (NCLS - 1);
        int c = task % (NCLS - 1);
        if (tid < TOPK) {
            unsigned km = keepmask[s][wrp];
            if ((km >> lane) & 1u) {
                int pos = __popc(km & ((1u << lane) - 1u));
#pragma unroll
                for (int q = 0; q < 6; q++)
                    if (q < wrp) pos += __popc(keepmask[s][q]);
                float4 bb = sbx4[s][tid];
                float* orow = out + ((((size_t)b * NCLS + (c + 1)) * TOPK) + pos) * 5;
                orow[0] = sscore[s][tid];
                orow[1] = bb.x; orow[2] = bb.y; orow[3] = bb.z; orow[4] = bb.w;
            }
        }
    }
}

// ---------------------------------------------------------------------------
extern "C" void kernel_launch(void* const* d_in, const int* in_sizes, int n_in,
                              void* d_out, int out_size) {
    const float* loc     = (const float*)d_in[0];  // [B,N,4]
    const float* conf    = (const float*)d_in[1];  // [B,N,21]
    const float* anchors = (const float*)d_in[2];  // [N,4]
    float* out = (float*)d_out;                    // [B,21,200,5]

    int total = in_sizes[0] / 4;          // B*N
    int B = total / NANCH;
    if (B > MAXB) B = MAXB;

    cudaMemsetAsync(d_out, 0, (size_t)out_size * sizeof(float), 0);

    zero_counters_kernel<<<(NTASKMAX + 255) / 256, 256>>>();
    dim3 gridA(NBLK, B);
    softmax_decode_kernel<<<gridA, 256>>>(loc, conf, anchors);
    int ntask = B * (NCLS - 1);                    // divisible by 4 (20 | ntask)
    topk_nms_kernel<<<ntask / TPC, 256>>>(conf, out);
}